// round 3
// baseline (speedup 1.0000x reference)
#include <cuda_runtime.h>
#include <math.h>

#define NV 50000
#define NE 25000
#define NNZ 200000
#define FIN 128
#define NHID 256
#define ND 4
#define NH1 16
#define NC 40

// ---------------- device scratch (static; no allocation) ----------------
// NOTE: these are ONLY ever referenced inside device code. Passing a
// __device__ array as a kernel argument from host code yields the host
// shadow address, which on GB300 (ATS-coherent) silently reads host zeros
// instead of faulting. Never do that.
__device__ float g_u1[FIN * 4];
__device__ float g_u2[FIN * 4];
__device__ float g_WA[FIN * 64];
__device__ float g_bbG[64];
__device__ float g_ba1[4];
__device__ float g_ba2[4];

__device__ float4 g_a1[NV];          // per-node sheaf pre-activation
__device__ float4 g_a2[NE];          // per-edge sheaf pre-activation
__device__ float4 g_s[NNZ];          // restriction-map scalars per incidence

__device__ int g_cnt_e[NE], g_cnt_v[NV];
__device__ int g_off_e[NE], g_off_v[NV];
__device__ int g_cur_e[NE], g_cur_v[NV];
__device__ int g_inc_e[NNZ], g_inc_v[NNZ];
__device__ int g_bsE[64], g_bsV[64];
__device__ float g_inv_e[NE], g_inv_v[NV];

__device__ float g_P0[NV * 64];      // Hn @ W0 (per-d), no b0
__device__ float g_m[NE * 64];       // hyperedge aggregation buffer
__device__ float g_H1[NV * 64];      // layer-1 activations
__device__ float g_T[NV * 64];       // H1 - agg(H1)

// ---------------- small setup kernels ----------------
__global__ void zero_misc() {
    int i = blockIdx.x * blockDim.x + threadIdx.x;
    if (i < NE) { g_cnt_e[i] = 0; g_cur_e[i] = 0; }
    if (i < NV) { g_cnt_v[i] = 0; g_cur_v[i] = 0; }
}

__global__ void count_deg(const int* __restrict__ node_idx,
                          const int* __restrict__ edge_idx) {
    int i = blockIdx.x * blockDim.x + threadIdx.x;
    if (i >= NNZ) return;
    atomicAdd(&g_cnt_e[edge_idx[i]], 1);
    atomicAdd(&g_cnt_v[node_idx[i]], 1);
}

__global__ void compute_inv() {
    int i = blockIdx.x * blockDim.x + threadIdx.x;
    if (i < NE) { int c = g_cnt_e[i]; g_inv_e[i] = c > 0 ? 1.0f / (float)c : 0.0f; }
    if (i < NV) { int c = g_cnt_v[i]; g_inv_v[i] = c > 0 ? 1.0f / (float)c : 0.0f; }
}

#define SCAN_B 1024
__device__ __forceinline__ void scan_local_dev(const int* __restrict__ in, int n,
                                               int* __restrict__ out,
                                               int* __restrict__ bsums) {
    __shared__ int sh[SCAN_B];
    int t = threadIdx.x;
    int i = blockIdx.x * SCAN_B + t;
    int v = (i < n) ? in[i] : 0;
    sh[t] = v;
    __syncthreads();
    for (int ofs = 1; ofs < SCAN_B; ofs <<= 1) {
        int add = (t >= ofs) ? sh[t - ofs] : 0;
        __syncthreads();
        sh[t] += add;
        __syncthreads();
    }
    if (i < n) out[i] = sh[t] - v;         // exclusive
    if (t == SCAN_B - 1) bsums[blockIdx.x] = sh[t];
}

__global__ void scan_local_e() { scan_local_dev(g_cnt_e, NE, g_off_e, g_bsE); }
__global__ void scan_local_v() { scan_local_dev(g_cnt_v, NV, g_off_v, g_bsV); }

__device__ __forceinline__ void scan_bsums_dev(int* bsums, int nb) {
    if (blockIdx.x == 0 && threadIdx.x == 0) {
        int acc = 0;
        for (int i = 0; i < nb; i++) { int v = bsums[i]; bsums[i] = acc; acc += v; }
    }
}
__global__ void scan_bsums_e(int nb) { scan_bsums_dev(g_bsE, nb); }
__global__ void scan_bsums_v(int nb) { scan_bsums_dev(g_bsV, nb); }

__global__ void scan_add_e() {
    int i = blockIdx.x * blockDim.x + threadIdx.x;
    if (i < NE) g_off_e[i] += g_bsE[i >> 10];
}
__global__ void scan_add_v() {
    int i = blockIdx.x * blockDim.x + threadIdx.x;
    if (i < NV) g_off_v[i] += g_bsV[i >> 10];
}

__global__ void fill_csr(const int* __restrict__ node_idx,
                         const int* __restrict__ edge_idx) {
    int i = blockIdx.x * blockDim.x + threadIdx.x;
    if (i >= NNZ) return;
    int e = edge_idx[i];
    int p = atomicAdd(&g_cur_e[e], 1);
    g_inc_e[g_off_e[e] + p] = i;
    int v = node_idx[i];
    int q = atomicAdd(&g_cur_v[v], 1);
    g_inc_v[g_off_v[v] + q] = i;
}

// ---------------- weight folding ----------------
__global__ void prep(const float* __restrict__ Wlin, const float* __restrict__ blin,
                     const float* __restrict__ w1, const float* __restrict__ w2,
                     const float* __restrict__ W0) {
    int b = blockIdx.x, t = threadIdx.x;
    if (b < FIN) {
        int f = b;
        if (t < 64) {
            int d = t >> 4, c = t & 15;
            const float* wl = Wlin + f * (ND * NHID) + d * NHID;
            float acc = 0.0f;
            #pragma unroll 8
            for (int h = 0; h < NHID; h++) acc += wl[h] * W0[h * NH1 + c];
            g_WA[f * 64 + t] = acc;
        } else if (t < 68) {
            int d = t - 64;
            const float* wl = Wlin + f * (ND * NHID) + d * NHID;
            float acc = 0.0f;
            #pragma unroll 8
            for (int h = 0; h < NHID; h++) acc += wl[h] * w1[h * ND + d];
            g_u1[f * 4 + d] = acc;
        } else if (t < 72) {
            int d = t - 68;
            const float* wl = Wlin + f * (ND * NHID) + d * NHID;
            float acc = 0.0f;
            #pragma unroll 8
            for (int h = 0; h < NHID; h++) acc += wl[h] * w2[h * ND + d];
            g_u2[f * 4 + d] = acc;
        }
    } else {
        if (t < 64) {
            int d = t >> 4, c = t & 15;
            const float* bl = blin + d * NHID;
            float acc = 0.0f;
            #pragma unroll 8
            for (int h = 0; h < NHID; h++) acc += bl[h] * W0[h * NH1 + c];
            g_bbG[t] = acc;
        } else if (t < 68) {
            int d = t - 64;
            const float* bl = blin + d * NHID;
            float acc = 0.0f;
            for (int h = 0; h < NHID; h++) acc += bl[h] * w1[h * ND + d];
            g_ba1[d] = acc;
        } else if (t < 72) {
            int d = t - 68;
            const float* bl = blin + d * NHID;
            float acc = 0.0f;
            for (int h = 0; h < NHID; h++) acc += bl[h] * w2[h * ND + d];
            g_ba2[d] = acc;
        }
    }
}

// ---------------- node GEMM: P0 = x@WA (+bbG), a1 = x@u1 (+ba1) ----------------
__global__ void node_gemm(const float* __restrict__ x) {
    __shared__ float shX[32][65];
    __shared__ float shW[64][64];
    __shared__ float shU[FIN * 4];
    int t = threadIdx.x;
    int tx = t & 15, ty = t >> 4;
    int row0 = blockIdx.x * 32;
    for (int i = t; i < FIN * 4; i += 128) shU[i] = g_u1[i];
    float acc[4][4] = {};
    float accA = 0.0f;
    int rA = t >> 2, dA = t & 3;
    for (int ch = 0; ch < 2; ch++) {
        int f0 = ch * 64;
        for (int i = t; i < 2048; i += 128) {
            int r = i >> 6, f = i & 63;
            int v = row0 + r;
            shX[r][f] = (v < NV) ? x[v * FIN + f0 + f] : 0.0f;
        }
        for (int i = t; i < 4096; i += 128) {
            int f = i >> 6, c = i & 63;
            shW[f][c] = g_WA[(f0 + f) * 64 + c];
        }
        __syncthreads();
        #pragma unroll 4
        for (int f = 0; f < 64; f++) {
            float xr[4], wc[4];
            #pragma unroll
            for (int q = 0; q < 4; q++) xr[q] = shX[ty + 8 * q][f];
            #pragma unroll
            for (int q = 0; q < 4; q++) wc[q] = shW[f][tx + 16 * q];
            #pragma unroll
            for (int a = 0; a < 4; a++)
                #pragma unroll
                for (int bq = 0; bq < 4; bq++) acc[a][bq] += xr[a] * wc[bq];
        }
        #pragma unroll 4
        for (int f = 0; f < 64; f++) accA += shX[rA][f] * shU[(f0 + f) * 4 + dA];
        __syncthreads();
    }
    #pragma unroll
    for (int a = 0; a < 4; a++) {
        int v = row0 + ty + 8 * a;
        if (v >= NV) continue;
        #pragma unroll
        for (int bq = 0; bq < 4; bq++) {
            int c = tx + 16 * bq;
            g_P0[v * 64 + c] = acc[a][bq] + g_bbG[c];
        }
    }
    int vA = row0 + rA;
    if (vA < NV) ((float*)g_a1)[vA * 4 + dA] = accA + g_ba1[dA];
}

// ---------------- edge GEMM: a2 = eattr @ u2 + ba2 ----------------
__global__ void edge_gemm(const float* __restrict__ eattr) {
    int id = blockIdx.x * blockDim.x + threadIdx.x;
    if (id >= NE * 4) return;
    int e = id >> 2, d = id & 3;
    const float* row = eattr + e * FIN;
    float acc = g_ba2[d];
    #pragma unroll 8
    for (int f = 0; f < FIN; f++) acc += row[f] * g_u2[f * 4 + d];
    ((float*)g_a2)[id] = acc;
}

// ---------------- sheaf scalars ----------------
__global__ void s_kernel(const int* __restrict__ node_idx,
                         const int* __restrict__ edge_idx,
                         const float* __restrict__ bs) {
    int i = blockIdx.x * blockDim.x + threadIdx.x;
    if (i >= NNZ) return;
    float4 A = g_a1[node_idx[i]];
    float4 B = g_a2[edge_idx[i]];
    float4 r;
    r.x = tanhf(A.x + B.x + bs[0]);
    r.y = tanhf(A.y + B.y + bs[1]);
    r.z = tanhf(A.z + B.z + bs[2]);
    r.w = tanhf(A.w + B.w + bs[3]);
    g_s[i] = r;
}

// ---------------- aggregation (warp per segment, CSR, no atomics) ----------------
// src: 0 -> read g_P0, 1 -> read g_H1 (resolved in DEVICE code)
__global__ void edge_agg(int src, const int* __restrict__ node_idx) {
    int w = (blockIdx.x * blockDim.x + threadIdx.x) >> 5;
    int lane = threadIdx.x & 31;
    if (w >= NE) return;
    const float* __restrict__ X = src ? g_H1 : g_P0;
    int beg = g_off_e[w], cnt = g_cnt_e[w];
    float acc0 = 0.0f, acc1 = 0.0f;
    for (int k = 0; k < cnt; k++) {
        int n = g_inc_e[beg + k];
        int v = node_idx[n];
        float4 s4 = g_s[n];
        float slo = (lane < 16) ? s4.x : s4.y;
        float shi = (lane < 16) ? s4.z : s4.w;
        const float* xr = X + v * 64;
        acc0 += slo * xr[lane];
        acc1 += shi * xr[lane + 32];
    }
    float inv = g_inv_e[w];
    g_m[w * 64 + lane]      = acc0 * inv;
    g_m[w * 64 + 32 + lane] = acc1 * inv;
}

// layer: 0 -> Base=g_P0, Out=g_H1, relu(+b0); 1 -> Base=g_H1, Out=g_T, no relu
__global__ void node_agg(int layer, const float* __restrict__ b0,
                         const int* __restrict__ edge_idx) {
    int w = (blockIdx.x * blockDim.x + threadIdx.x) >> 5;
    int lane = threadIdx.x & 31;
    if (w >= NV) return;
    const float* __restrict__ Base = layer ? g_H1 : g_P0;
    float* __restrict__ Out = layer ? g_T : g_H1;
    int beg = g_off_v[w], cnt = g_cnt_v[w];
    float acc0 = 0.0f, acc1 = 0.0f;
    for (int k = 0; k < cnt; k++) {
        int n = g_inc_v[beg + k];
        int e = edge_idx[n];
        float4 s4 = g_s[n];
        float slo = (lane < 16) ? s4.x : s4.y;
        float shi = (lane < 16) ? s4.z : s4.w;
        const float* mr = g_m + e * 64;
        acc0 += slo * mr[lane];
        acc1 += shi * mr[lane + 32];
    }
    float inv = g_inv_v[w];
    float o0 = Base[w * 64 + lane]      - acc0 * inv;
    float o1 = Base[w * 64 + 32 + lane] - acc1 * inv;
    if (layer == 0) {
        float bb = b0[lane & 15];
        o0 = fmaxf(o0 + bb, 0.0f);
        o1 = fmaxf(o1 + bb, 0.0f);
    }
    Out[w * 64 + lane]      = o0;
    Out[w * 64 + 32 + lane] = o1;
}

// ---------------- final fused: Z = relu(T @ blockdiag(W1) + b1); out = Z @ W2 ----------------
// 16-row tile, 320 threads, static shared (42,976 B < 48 KB).
__global__ void final_kernel(const float* __restrict__ W1, const float* __restrict__ b1,
                             const float* __restrict__ W2, float* __restrict__ out) {
    __shared__ float shW1[640];        // 16 x 40
    __shared__ float shb1[40];
    __shared__ float shW2[6400];       // 160 x 40
    __shared__ float shT[16 * 65];     // 16 rows x 64 ch (padded)
    __shared__ float shZ[16 * 164];    // 16 rows x 160 ch (padded)
    int t = threadIdx.x;
    for (int i = t; i < 640; i += 320) shW1[i] = W1[i];
    for (int i = t; i < 40; i += 320) shb1[i] = b1[i];
    for (int i = t; i < 6400; i += 320) shW2[i] = W2[i];
    int row0 = blockIdx.x * 16;
    for (int i = t; i < 1024; i += 320) {
        int r = i >> 6, c = i & 63;
        int v = row0 + r;
        shT[r * 65 + c] = (v < NV) ? g_T[v * 64 + c] : 0.0f;
    }
    __syncthreads();
    // Phase B: Z[r, d*40+j] = relu( sum_k T[r, d*16+k] * W1[k,j] + b1[j] )
    {
        int tx = t % 40, ty = t / 40;      // ty in [0,8)
        int d = tx / 10, cl = tx % 10;
        float zacc[2][4] = {};
        #pragma unroll
        for (int k = 0; k < 16; k++) {
            float tv[2], wv[4];
            #pragma unroll
            for (int a = 0; a < 2; a++) tv[a] = shT[(ty + 8 * a) * 65 + d * 16 + k];
            #pragma unroll
            for (int q = 0; q < 4; q++) wv[q] = shW1[k * 40 + cl + 10 * q];
            #pragma unroll
            for (int a = 0; a < 2; a++)
                #pragma unroll
                for (int q = 0; q < 4; q++) zacc[a][q] += tv[a] * wv[q];
        }
        #pragma unroll
        for (int a = 0; a < 2; a++)
            #pragma unroll
            for (int q = 0; q < 4; q++) {
                int j = cl + 10 * q;
                shZ[(ty + 8 * a) * 164 + d * 40 + j] = fmaxf(zacc[a][q] + shb1[j], 0.0f);
            }
    }
    __syncthreads();
    // Phase C: out[r, j] = sum_{k<160} Z[r,k] * W2[k,j]; all 320 threads active.
    {
        int col = t % 40, rg = t / 40;     // rg in [0,8)
        float oacc[2] = {0.0f, 0.0f};
        #pragma unroll 4
        for (int k = 0; k < 160; k++) {
            float w = shW2[k * 40 + col];
            oacc[0] += shZ[rg * 164 + k] * w;
            oacc[1] += shZ[(rg + 8) * 164 + k] * w;
        }
        int v0 = row0 + rg, v1 = row0 + rg + 8;
        if (v0 < NV) out[v0 * NC + col] = oacc[0];
        if (v1 < NV) out[v1 * NC + col] = oacc[1];
    }
}

// ---------------- launch ----------------
extern "C" void kernel_launch(void* const* d_in, const int* in_sizes, int n_in,
                              void* d_out, int out_size) {
    const float* x        = (const float*)d_in[0];
    const float* eattr    = (const float*)d_in[1];
    const int*   node_idx = (const int*)d_in[2];
    const int*   edge_idx = (const int*)d_in[3];
    const float* Wlin     = (const float*)d_in[4];
    const float* blin     = (const float*)d_in[5];
    const float* w1       = (const float*)d_in[6];
    const float* w2       = (const float*)d_in[7];
    const float* bs       = (const float*)d_in[8];
    const float* W0       = (const float*)d_in[9];
    const float* b0       = (const float*)d_in[10];
    const float* W1       = (const float*)d_in[11];
    const float* b1       = (const float*)d_in[12];
    const float* W2       = (const float*)d_in[13];
    float* out = (float*)d_out;

    int gV = (NV + 255) / 256;
    int gZ = (NNZ + 255) / 256;
    int nbE = (NE + SCAN_B - 1) / SCAN_B;     // 25
    int nbV = (NV + SCAN_B - 1) / SCAN_B;     // 49

    // graph structure (recomputed every call; deterministic work)
    zero_misc<<<gV, 256>>>();
    count_deg<<<gZ, 256>>>(node_idx, edge_idx);
    compute_inv<<<gV, 256>>>();
    scan_local_e<<<nbE, SCAN_B>>>();
    scan_bsums_e<<<1, 32>>>(nbE);
    scan_add_e<<<(NE + 255) / 256, 256>>>();
    scan_local_v<<<nbV, SCAN_B>>>();
    scan_bsums_v<<<1, 32>>>(nbV);
    scan_add_v<<<gV, 256>>>();
    fill_csr<<<gZ, 256>>>(node_idx, edge_idx);

    // folded weights + lifted features
    prep<<<FIN + 1, 128>>>(Wlin, blin, w1, w2, W0);
    node_gemm<<<(NV + 31) / 32, 128>>>(x);
    edge_gemm<<<(NE * 4 + 127) / 128, 128>>>(eattr);
    s_kernel<<<gZ, 256>>>(node_idx, edge_idx, bs);

    // layer 1: H1 = relu(P0 - agg(P0) + b0)
    edge_agg<<<(NE * 32 + 255) / 256, 256>>>(0, node_idx);
    node_agg<<<(NV * 32 + 255) / 256, 256>>>(0, b0, edge_idx);

    // layer 2: T = H1 - agg(H1)
    edge_agg<<<(NE * 32 + 255) / 256, 256>>>(1, node_idx);
    node_agg<<<(NV * 32 + 255) / 256, 256>>>(1, b0, edge_idx);

    // fused: out = relu(T @ blockdiag(W1) + b1) @ W2
    final_kernel<<<(NV + 15) / 16, 320>>>(W1, b1, W2, out);
}

// round 4
// speedup vs baseline: 1.1008x; 1.1008x over previous
#include <cuda_runtime.h>
#include <math.h>

#define NV 50000
#define NE 25000
#define NNZ 200000
#define FIN 128
#define NHID 256
#define ND 4
#define NH1 16
#define NC 40

// ---------------- device scratch (static; no allocation) ----------------
// NOTE: only ever referenced inside device code. Passing a __device__ array
// as a kernel argument from host code yields the host shadow address, which
// on GB300 (ATS-coherent) silently reads host zeros instead of faulting.
__device__ float g_u1[FIN * 4];
__device__ float g_u2[FIN * 4];
__device__ float g_WA[FIN * 64];
__device__ float g_bbG[64];
__device__ float g_ba1[4];
__device__ float g_ba2[4];

__device__ float4 g_a1[NV];
__device__ float4 g_a2[NE];
__device__ float4 g_s[NNZ];

__device__ int g_cnt_e[NE], g_cnt_v[NV];
__device__ int g_off_e[NE], g_off_v[NV];
__device__ int g_cur_e[NE], g_cur_v[NV];
__device__ int g_inc_e[NNZ], g_inc_v[NNZ];
__device__ int g_bsE[64], g_bsV[64];
__device__ float g_inv_e[NE], g_inv_v[NV];

__device__ float g_P0[NV * 64];
__device__ float g_m[NE * 64];
__device__ float g_H1[NV * 64];
__device__ float g_T[NV * 64];

// ---------------- setup kernels ----------------
__global__ void zero_misc() {
    int i = blockIdx.x * blockDim.x + threadIdx.x;
    if (i < NE) { g_cnt_e[i] = 0; g_cur_e[i] = 0; }
    if (i < NV) { g_cnt_v[i] = 0; g_cur_v[i] = 0; }
}

__global__ void count_deg(const int* __restrict__ node_idx,
                          const int* __restrict__ edge_idx) {
    int i = blockIdx.x * blockDim.x + threadIdx.x;
    if (i >= NNZ) return;
    atomicAdd(&g_cnt_e[edge_idx[i]], 1);
    atomicAdd(&g_cnt_v[node_idx[i]], 1);
}

// warp-shuffle block scan (1024 thr = 32 warps); also emits 1/deg
__device__ __forceinline__ void scan_local_dev(const int* __restrict__ in, int n,
                                               int* __restrict__ out,
                                               float* __restrict__ inv,
                                               int* __restrict__ bsums) {
    __shared__ int wsum[32];
    int t = threadIdx.x;
    int i = blockIdx.x * 1024 + t;
    int v = (i < n) ? in[i] : 0;
    if (i < n) inv[i] = v > 0 ? 1.0f / (float)v : 0.0f;
    int lane = t & 31, wid = t >> 5;
    int xv = v;
    #pragma unroll
    for (int o = 1; o < 32; o <<= 1) {
        int y = __shfl_up_sync(0xFFFFFFFFu, xv, o);
        if (lane >= o) xv += y;
    }
    if (lane == 31) wsum[wid] = xv;
    __syncthreads();
    if (wid == 0) {
        int s = wsum[lane];
        #pragma unroll
        for (int o = 1; o < 32; o <<= 1) {
            int y = __shfl_up_sync(0xFFFFFFFFu, s, o);
            if (lane >= o) s += y;
        }
        wsum[lane] = s;
    }
    __syncthreads();
    int base = wid > 0 ? wsum[wid - 1] : 0;
    if (i < n) out[i] = base + xv - v;          // exclusive
    if (t == 1023) bsums[blockIdx.x] = base + xv;
}

__global__ void scan_local_e() { scan_local_dev(g_cnt_e, NE, g_off_e, g_inv_e, g_bsE); }
__global__ void scan_local_v() { scan_local_dev(g_cnt_v, NV, g_off_v, g_inv_v, g_bsV); }

// per-block: prefix of bsums computed by a warp, then added (merges old scan_bsums+scan_add)
__device__ __forceinline__ void scan_fix_dev(int* __restrict__ off, int n,
                                             const int* __restrict__ bsums) {
    __shared__ int pfx;
    int b = blockIdx.x;
    if (threadIdx.x < 32) {
        int v = 0;
        for (int j = threadIdx.x; j < b; j += 32) v += bsums[j];
        #pragma unroll
        for (int o = 16; o; o >>= 1) v += __shfl_down_sync(0xFFFFFFFFu, v, o);
        if (threadIdx.x == 0) pfx = v;
    }
    __syncthreads();
    int i = b * 1024 + threadIdx.x;
    if (i < n) off[i] += pfx;
}
__global__ void scan_fix_e() { scan_fix_dev(g_off_e, NE, g_bsE); }
__global__ void scan_fix_v() { scan_fix_dev(g_off_v, NV, g_bsV); }

__global__ void fill_csr(const int* __restrict__ node_idx,
                         const int* __restrict__ edge_idx) {
    int i = blockIdx.x * blockDim.x + threadIdx.x;
    if (i >= NNZ) return;
    int e = edge_idx[i];
    int p = atomicAdd(&g_cur_e[e], 1);
    g_inc_e[g_off_e[e] + p] = i;
    int v = node_idx[i];
    int q = atomicAdd(&g_cur_v[v], 1);
    g_inc_v[g_off_v[v] + q] = i;
}

// ---------------- weight folding ----------------
__global__ void prep(const float* __restrict__ Wlin, const float* __restrict__ blin,
                     const float* __restrict__ w1, const float* __restrict__ w2,
                     const float* __restrict__ W0) {
    int b = blockIdx.x, t = threadIdx.x;
    if (b < FIN) {
        int f = b;
        if (t < 64) {
            int d = t >> 4, c = t & 15;
            const float* wl = Wlin + f * (ND * NHID) + d * NHID;
            float acc = 0.0f;
            #pragma unroll 8
            for (int h = 0; h < NHID; h++) acc += wl[h] * W0[h * NH1 + c];
            g_WA[f * 64 + t] = acc;
        } else if (t < 68) {
            int d = t - 64;
            const float* wl = Wlin + f * (ND * NHID) + d * NHID;
            float acc = 0.0f;
            #pragma unroll 8
            for (int h = 0; h < NHID; h++) acc += wl[h] * w1[h * ND + d];
            g_u1[f * 4 + d] = acc;
        } else if (t < 72) {
            int d = t - 68;
            const float* wl = Wlin + f * (ND * NHID) + d * NHID;
            float acc = 0.0f;
            #pragma unroll 8
            for (int h = 0; h < NHID; h++) acc += wl[h] * w2[h * ND + d];
            g_u2[f * 4 + d] = acc;
        }
    } else {
        if (t < 64) {
            int d = t >> 4, c = t & 15;
            const float* bl = blin + d * NHID;
            float acc = 0.0f;
            #pragma unroll 8
            for (int h = 0; h < NHID; h++) acc += bl[h] * W0[h * NH1 + c];
            g_bbG[t] = acc;
        } else if (t < 68) {
            int d = t - 64;
            const float* bl = blin + d * NHID;
            float acc = 0.0f;
            for (int h = 0; h < NHID; h++) acc += bl[h] * w1[h * ND + d];
            g_ba1[d] = acc;
        } else if (t < 72) {
            int d = t - 68;
            const float* bl = blin + d * NHID;
            float acc = 0.0f;
            for (int h = 0; h < NHID; h++) acc += bl[h] * w2[h * ND + d];
            g_ba2[d] = acc;
        }
    }
}

// ---------------- node GEMM: P0 = x@WA (+bbG), a1 = x@u1 (+ba1) ----------------
// float4-vectorized LDS (transposed W tile): 8 LDS.128 per 64 FMA.
__global__ __launch_bounds__(128) void node_gemm(const float* __restrict__ x) {
    __shared__ float shX[32][68];
    __shared__ float shWT[64][68];
    __shared__ float shUT[4][132];
    int t = threadIdx.x;
    int tx = t & 15, ty = t >> 4;
    int row0 = blockIdx.x * 32;
    for (int i = t; i < 512; i += 128) {
        int d = i >> 7, f = i & 127;
        shUT[d][f] = g_u1[f * 4 + d];
    }
    float acc[4][4] = {};
    float accA = 0.0f;
    int rA = t >> 2, dA = t & 3;
    for (int ch = 0; ch < 2; ch++) {
        int f0 = ch * 64;
        __syncthreads();
        for (int i = t; i < 2048; i += 128) {
            int r = i >> 6, f = i & 63;
            int v = row0 + r;
            shX[r][f] = (v < NV) ? x[v * FIN + f0 + f] : 0.0f;
        }
        for (int i = t; i < 4096; i += 128) {
            int f = i >> 6, c = i & 63;
            shWT[c][f] = g_WA[(f0 + f) * 64 + c];
        }
        __syncthreads();
        #pragma unroll
        for (int f4 = 0; f4 < 16; f4++) {
            float4 xr[4], wv[4];
            #pragma unroll
            for (int a = 0; a < 4; a++) xr[a] = *(const float4*)&shX[ty + 8 * a][f4 * 4];
            #pragma unroll
            for (int q = 0; q < 4; q++) wv[q] = *(const float4*)&shWT[tx + 16 * q][f4 * 4];
            #pragma unroll
            for (int a = 0; a < 4; a++)
                #pragma unroll
                for (int q = 0; q < 4; q++)
                    acc[a][q] += xr[a].x * wv[q].x + xr[a].y * wv[q].y
                               + xr[a].z * wv[q].z + xr[a].w * wv[q].w;
        }
        #pragma unroll
        for (int f4 = 0; f4 < 16; f4++) {
            float4 xv = *(const float4*)&shX[rA][f4 * 4];
            float4 uv = *(const float4*)&shUT[dA][f0 + f4 * 4];
            accA += xv.x * uv.x + xv.y * uv.y + xv.z * uv.z + xv.w * uv.w;
        }
    }
    #pragma unroll
    for (int a = 0; a < 4; a++) {
        int v = row0 + ty + 8 * a;
        if (v >= NV) continue;
        #pragma unroll
        for (int q = 0; q < 4; q++) {
            int c = tx + 16 * q;
            g_P0[v * 64 + c] = acc[a][q] + g_bbG[c];
        }
    }
    int vA = row0 + rA;
    if (vA < NV) ((float*)g_a1)[vA * 4 + dA] = accA + g_ba1[dA];
}

// ---------------- edge GEMM: a2 = eattr @ u2 + ba2 ----------------
__global__ void edge_gemm(const float* __restrict__ eattr) {
    int id = blockIdx.x * blockDim.x + threadIdx.x;
    if (id >= NE * 4) return;
    int e = id >> 2, d = id & 3;
    const float* row = eattr + e * FIN;
    float acc = g_ba2[d];
    #pragma unroll 8
    for (int f = 0; f < FIN; f++) acc += row[f] * g_u2[f * 4 + d];
    ((float*)g_a2)[id] = acc;
}

// ---------------- sheaf scalars ----------------
__global__ void s_kernel(const int* __restrict__ node_idx,
                         const int* __restrict__ edge_idx,
                         const float* __restrict__ bs) {
    int i = blockIdx.x * blockDim.x + threadIdx.x;
    if (i >= NNZ) return;
    float4 A = g_a1[node_idx[i]];
    float4 B = g_a2[edge_idx[i]];
    float4 r;
    r.x = tanhf(A.x + B.x + bs[0]);
    r.y = tanhf(A.y + B.y + bs[1]);
    r.z = tanhf(A.z + B.z + bs[2]);
    r.w = tanhf(A.w + B.w + bs[3]);
    g_s[i] = r;
}

// ---------------- aggregation (warp per segment, CSR, no atomics) ----------------
__global__ void edge_agg(int src, const int* __restrict__ node_idx) {
    int w = (blockIdx.x * blockDim.x + threadIdx.x) >> 5;
    int lane = threadIdx.x & 31;
    if (w >= NE) return;
    const float* __restrict__ X = src ? g_H1 : g_P0;
    int beg = g_off_e[w], cnt = g_cnt_e[w];
    float acc0 = 0.0f, acc1 = 0.0f;
    for (int k = 0; k < cnt; k++) {
        int n = g_inc_e[beg + k];
        int v = node_idx[n];
        float4 s4 = g_s[n];
        float slo = (lane < 16) ? s4.x : s4.y;
        float shi = (lane < 16) ? s4.z : s4.w;
        const float* xr = X + v * 64;
        acc0 += slo * xr[lane];
        acc1 += shi * xr[lane + 32];
    }
    float inv = g_inv_e[w];
    g_m[w * 64 + lane]      = acc0 * inv;
    g_m[w * 64 + 32 + lane] = acc1 * inv;
}

__global__ void node_agg(int layer, const float* __restrict__ b0,
                         const int* __restrict__ edge_idx) {
    int w = (blockIdx.x * blockDim.x + threadIdx.x) >> 5;
    int lane = threadIdx.x & 31;
    if (w >= NV) return;
    const float* __restrict__ Base = layer ? g_H1 : g_P0;
    float* __restrict__ Out = layer ? g_T : g_H1;
    int beg = g_off_v[w], cnt = g_cnt_v[w];
    float acc0 = 0.0f, acc1 = 0.0f;
    for (int k = 0; k < cnt; k++) {
        int n = g_inc_v[beg + k];
        int e = edge_idx[n];
        float4 s4 = g_s[n];
        float slo = (lane < 16) ? s4.x : s4.y;
        float shi = (lane < 16) ? s4.z : s4.w;
        const float* mr = g_m + e * 64;
        acc0 += slo * mr[lane];
        acc1 += shi * mr[lane + 32];
    }
    float inv = g_inv_v[w];
    float o0 = Base[w * 64 + lane]      - acc0 * inv;
    float o1 = Base[w * 64 + 32 + lane] - acc1 * inv;
    if (layer == 0) {
        float bb = b0[lane & 15];
        o0 = fmaxf(o0 + bb, 0.0f);
        o1 = fmaxf(o1 + bb, 0.0f);
    }
    Out[w * 64 + lane]      = o0;
    Out[w * 64 + 32 + lane] = o1;
}

// ---------------- final fused: out = relu(T @ blockdiag(W1) + b1) @ W2 ----------------
// 64-row tile, 320 threads, dynamic smem (89.6 KB). Phase C: 4x4 register
// tiles + split-K halves + float4 LDS from transposed W2 (0.5 loads/MAC).
#define FK2_FLOATS (640 + 40 + 40 * 172 + 64 * 68 + 64 * 164)
__global__ __launch_bounds__(320, 2)
void final_kernel(const float* __restrict__ W1, const float* __restrict__ b1,
                  const float* __restrict__ W2, float* __restrict__ out) {
    extern __shared__ float sh[];
    float* shW1  = sh;                 // 640
    float* shb1  = sh + 640;           // 40
    float* shW2T = sh + 680;           // [j][k] stride 172 -> 6880
    float* shT   = sh + 7560;          // [r][c] stride 68 -> 4352 (reused as partials)
    float* shZ   = sh + 11912;         // [r][k] stride 164 -> 10496
    int t = threadIdx.x;
    for (int i = t; i < 640; i += 320) shW1[i] = W1[i];
    for (int i = t; i < 40; i += 320) shb1[i] = b1[i];
    for (int i = t; i < 6400; i += 320) {
        int k = i / 40, j = i % 40;
        shW2T[j * 172 + k] = W2[i];
    }
    int row0 = blockIdx.x * 64;
    for (int i = t; i < 4096; i += 320) {
        int r = i >> 6, c = i & 63;
        int v = row0 + r;
        shT[r * 68 + c] = (v < NV) ? g_T[v * 64 + c] : 0.0f;
    }
    __syncthreads();
    // Phase B: Z = relu(T @ blockdiag(W1) + b1); 8 rows x 4 cols per thread
    {
        int tx = t % 40, ty = t / 40;      // ty 0..7
        int d = tx / 10, cl = tx % 10;
        float zacc[8][4] = {};
        #pragma unroll
        for (int k = 0; k < 16; k++) {
            float tv[8], wv[4];
            #pragma unroll
            for (int a = 0; a < 8; a++) tv[a] = shT[(ty + 8 * a) * 68 + d * 16 + k];
            #pragma unroll
            for (int q = 0; q < 4; q++) wv[q] = shW1[k * 40 + cl + 10 * q];
            #pragma unroll
            for (int a = 0; a < 8; a++)
                #pragma unroll
                for (int q = 0; q < 4; q++) zacc[a][q] += tv[a] * wv[q];
        }
        #pragma unroll
        for (int a = 0; a < 8; a++)
            #pragma unroll
            for (int q = 0; q < 4; q++) {
                int j = cl + 10 * q;
                shZ[(ty + 8 * a) * 164 + d * 40 + j] = fmaxf(zacc[a][q] + shb1[j], 0.0f);
            }
    }
    __syncthreads();
    // Phase C: out = Z @ W2; 160 groups x (4 rows x 4 cols), k split in halves
    {
        int g = t % 160, kh = t / 160;     // kh 0,1
        int col4 = g % 10, row4 = g / 10;  // row4 0..15
        int r0 = row4 * 4, j0 = col4 * 4;
        float oa[4][4] = {};
        int kbeg = kh * 80;
        #pragma unroll 5
        for (int k4 = 0; k4 < 20; k4++) {
            int k = kbeg + k4 * 4;
            float4 zv[4], wv[4];
            #pragma unroll
            for (int a = 0; a < 4; a++) zv[a] = *(const float4*)&shZ[(r0 + a) * 164 + k];
            #pragma unroll
            for (int q = 0; q < 4; q++) wv[q] = *(const float4*)&shW2T[(j0 + q) * 172 + k];
            #pragma unroll
            for (int a = 0; a < 4; a++)
                #pragma unroll
                for (int q = 0; q < 4; q++)
                    oa[a][q] += zv[a].x * wv[q].x + zv[a].y * wv[q].y
                              + zv[a].z * wv[q].z + zv[a].w * wv[q].w;
        }
        float* shP = shT;                   // reuse (shT dead after phase B)
        if (kh == 0) {
            #pragma unroll
            for (int a = 0; a < 4; a++)
                #pragma unroll
                for (int q = 0; q < 4; q++) shP[g * 16 + a * 4 + q] = oa[a][q];
        }
        __syncthreads();
        if (kh == 1) {
            #pragma unroll
            for (int a = 0; a < 4; a++) {
                int v = row0 + r0 + a;
                if (v < NV) {
                    #pragma unroll
                    for (int q = 0; q < 4; q++)
                        out[v * NC + j0 + q] = oa[a][q] + shP[g * 16 + a * 4 + q];
                }
            }
        }
    }
}

// ---------------- launch ----------------
extern "C" void kernel_launch(void* const* d_in, const int* in_sizes, int n_in,
                              void* d_out, int out_size) {
    const float* x        = (const float*)d_in[0];
    const float* eattr    = (const float*)d_in[1];
    const int*   node_idx = (const int*)d_in[2];
    const int*   edge_idx = (const int*)d_in[3];
    const float* Wlin     = (const float*)d_in[4];
    const float* blin     = (const float*)d_in[5];
    const float* w1       = (const float*)d_in[6];
    const float* w2       = (const float*)d_in[7];
    const float* bs       = (const float*)d_in[8];
    const float* W0       = (const float*)d_in[9];
    const float* b0       = (const float*)d_in[10];
    const float* W1       = (const float*)d_in[11];
    const float* b1       = (const float*)d_in[12];
    const float* W2       = (const float*)d_in[13];
    float* out = (float*)d_out;

    static int fk_attr_done = 0;
    if (!fk_attr_done) {
        cudaFuncSetAttribute(final_kernel, cudaFuncAttributeMaxDynamicSharedMemorySize,
                             FK2_FLOATS * 4);
        fk_attr_done = 1;
    }

    int gV = (NV + 255) / 256;
    int gZ = (NNZ + 255) / 256;
    int nbE = (NE + 1023) / 1024;     // 25
    int nbV = (NV + 1023) / 1024;     // 49

    // graph structure
    zero_misc<<<gV, 256>>>();
    count_deg<<<gZ, 256>>>(node_idx, edge_idx);
    scan_local_e<<<nbE, 1024>>>();
    scan_local_v<<<nbV, 1024>>>();
    scan_fix_e<<<nbE, 1024>>>();
    scan_fix_v<<<nbV, 1024>>>();
    fill_csr<<<gZ, 256>>>(node_idx, edge_idx);

    // folded weights + lifted features
    prep<<<FIN + 1, 128>>>(Wlin, blin, w1, w2, W0);
    node_gemm<<<(NV + 31) / 32, 128>>>(x);
    edge_gemm<<<(NE * 4 + 127) / 128, 128>>>(eattr);
    s_kernel<<<gZ, 256>>>(node_idx, edge_idx, bs);

    // layer 1
    edge_agg<<<(NE * 32 + 255) / 256, 256>>>(0, node_idx);
    node_agg<<<(NV * 32 + 255) / 256, 256>>>(0, b0, edge_idx);

    // layer 2
    edge_agg<<<(NE * 32 + 255) / 256, 256>>>(1, node_idx);
    node_agg<<<(NV * 32 + 255) / 256, 256>>>(1, b0, edge_idx);

    // fused final
    final_kernel<<<(NV + 63) / 64, 320, FK2_FLOATS * 4>>>(W1, b1, W2, out);
}

// round 5
// speedup vs baseline: 1.3306x; 1.2088x over previous
#include <cuda_runtime.h>
#include <math.h>

#define NV 50000
#define NE 25000
#define NNZ 200000
#define FIN 128
#define NHID 256
#define ND 4
#define NH1 16
#define NC 40

// ---------------- device scratch (static; no allocation) ----------------
// Only ever referenced inside device code (GB300 ATS makes host-shadow
// dereference silently read zeros — never pass these as kernel args).
__device__ float g_u1[FIN * 4];
__device__ float g_u2[FIN * 4];
__device__ float g_WA[FIN * 64];
__device__ float g_bbG[64];
__device__ float g_ba1[4];
__device__ float g_ba2[4];

__device__ float4 g_a1[NV];
__device__ float4 g_a2[NE];

__device__ int g_cnt_e[NE], g_cnt_v[NV];
__device__ int g_off_e[NE], g_off_v[NV];
__device__ int g_cur_e[NE], g_cur_v[NV];
__device__ int g_bsE[64], g_bsV[64];
__device__ float g_inv_e[NE], g_inv_v[NV];

// CSR payload (index + restriction scalars resolved into CSR order)
__device__ int g_vid_e[NNZ];      // node id per edge-CSR slot
__device__ int g_eid_v[NNZ];      // edge id per node-CSR slot
__device__ int g_slot_e[NNZ];
__device__ int g_slot_v[NNZ];
__device__ float4 g_se[NNZ];
__device__ float4 g_sv[NNZ];

__device__ float g_P0[NV * 64];
__device__ float g_m[NE * 64];
__device__ float g_H1[NV * 64];
__device__ float g_T[NV * 64];

// ---------------- init: zero counters + weight folding (fused) ----------------
#define ZBLK 391    // ceil(NV/128)
__global__ __launch_bounds__(128) void init_kernel(
    const float* __restrict__ Wlin, const float* __restrict__ blin,
    const float* __restrict__ w1, const float* __restrict__ w2,
    const float* __restrict__ W0) {
    int b = blockIdx.x, t = threadIdx.x;
    if (b < ZBLK) {
        int i = b * 128 + t;
        if (i < NE) { g_cnt_e[i] = 0; g_cur_e[i] = 0; }
        if (i < NV) { g_cnt_v[i] = 0; g_cur_v[i] = 0; }
        return;
    }
    int pb = b - ZBLK;                 // 0..128 (129 blocks)
    if (pb < FIN) {
        int f = pb;
        if (t < 64) {
            int d = t >> 4, c = t & 15;
            const float* wl = Wlin + f * (ND * NHID) + d * NHID;
            float acc = 0.0f;
            #pragma unroll 8
            for (int h = 0; h < NHID; h++) acc += wl[h] * W0[h * NH1 + c];
            g_WA[f * 64 + t] = acc;
        } else if (t < 68) {
            int d = t - 64;
            const float* wl = Wlin + f * (ND * NHID) + d * NHID;
            float acc = 0.0f;
            #pragma unroll 8
            for (int h = 0; h < NHID; h++) acc += wl[h] * w1[h * ND + d];
            g_u1[f * 4 + d] = acc;
        } else if (t < 72) {
            int d = t - 68;
            const float* wl = Wlin + f * (ND * NHID) + d * NHID;
            float acc = 0.0f;
            #pragma unroll 8
            for (int h = 0; h < NHID; h++) acc += wl[h] * w2[h * ND + d];
            g_u2[f * 4 + d] = acc;
        }
    } else {
        if (t < 64) {
            int d = t >> 4, c = t & 15;
            const float* bl = blin + d * NHID;
            float acc = 0.0f;
            #pragma unroll 8
            for (int h = 0; h < NHID; h++) acc += bl[h] * W0[h * NH1 + c];
            g_bbG[t] = acc;
        } else if (t < 68) {
            int d = t - 64;
            const float* bl = blin + d * NHID;
            float acc = 0.0f;
            for (int h = 0; h < NHID; h++) acc += bl[h] * w1[h * ND + d];
            g_ba1[d] = acc;
        } else if (t < 72) {
            int d = t - 68;
            const float* bl = blin + d * NHID;
            float acc = 0.0f;
            for (int h = 0; h < NHID; h++) acc += bl[h] * w2[h * ND + d];
            g_ba2[d] = acc;
        }
    }
}

__global__ void count_deg(const int* __restrict__ node_idx,
                          const int* __restrict__ edge_idx) {
    int i = blockIdx.x * blockDim.x + threadIdx.x;
    if (i >= NNZ) return;
    atomicAdd(&g_cnt_e[edge_idx[i]], 1);
    atomicAdd(&g_cnt_v[node_idx[i]], 1);
}

// ---------------- fused scans (blocks 0..24: edges, 25..73: nodes) ----------------
#define NBE 25
#define NBV 49
__device__ __forceinline__ void scan_local_dev(const int* __restrict__ in, int n,
                                               int* __restrict__ out,
                                               float* __restrict__ inv,
                                               int* __restrict__ bsums, int blk) {
    __shared__ int wsum[32];
    int t = threadIdx.x;
    int i = blk * 1024 + t;
    int v = (i < n) ? in[i] : 0;
    if (i < n) inv[i] = v > 0 ? 1.0f / (float)v : 0.0f;
    int lane = t & 31, wid = t >> 5;
    int xv = v;
    #pragma unroll
    for (int o = 1; o < 32; o <<= 1) {
        int y = __shfl_up_sync(0xFFFFFFFFu, xv, o);
        if (lane >= o) xv += y;
    }
    if (lane == 31) wsum[wid] = xv;
    __syncthreads();
    if (wid == 0) {
        int s = wsum[lane];
        #pragma unroll
        for (int o = 1; o < 32; o <<= 1) {
            int y = __shfl_up_sync(0xFFFFFFFFu, s, o);
            if (lane >= o) s += y;
        }
        wsum[lane] = s;
    }
    __syncthreads();
    int base = wid > 0 ? wsum[wid - 1] : 0;
    if (i < n) out[i] = base + xv - v;
    if (t == 1023) bsums[blk] = base + xv;
}

__global__ void scan_all() {
    if (blockIdx.x < NBE)
        scan_local_dev(g_cnt_e, NE, g_off_e, g_inv_e, g_bsE, blockIdx.x);
    else
        scan_local_dev(g_cnt_v, NV, g_off_v, g_inv_v, g_bsV, blockIdx.x - NBE);
}

__device__ __forceinline__ void scan_fix_dev(int* __restrict__ off, int n,
                                             const int* __restrict__ bsums, int blk) {
    __shared__ int pfx;
    if (threadIdx.x < 32) {
        int v = 0;
        for (int j = (int)threadIdx.x; j < blk; j += 32) v += bsums[j];
        #pragma unroll
        for (int o = 16; o; o >>= 1) v += __shfl_down_sync(0xFFFFFFFFu, v, o);
        if (threadIdx.x == 0) pfx = v;
    }
    __syncthreads();
    int i = blk * 1024 + threadIdx.x;
    if (i < n) off[i] += pfx;
}
__global__ void fix_all() {
    if (blockIdx.x < NBE) scan_fix_dev(g_off_e, NE, g_bsE, blockIdx.x);
    else                  scan_fix_dev(g_off_v, NV, g_bsV, blockIdx.x - NBE);
}

__global__ void fill_csr(const int* __restrict__ node_idx,
                         const int* __restrict__ edge_idx) {
    int i = blockIdx.x * blockDim.x + threadIdx.x;
    if (i >= NNZ) return;
    int e = edge_idx[i];
    int v = node_idx[i];
    int p = atomicAdd(&g_cur_e[e], 1);
    int pos = g_off_e[e] + p;
    g_vid_e[pos] = v;
    g_slot_e[i] = pos;
    int q = atomicAdd(&g_cur_v[v], 1);
    int pos2 = g_off_v[v] + q;
    g_eid_v[pos2] = e;
    g_slot_v[i] = pos2;
}

// ---------------- fused GEMMs: node (P0, a1) + edge (a2) ----------------
#define NODE_BLOCKS 1563     // ceil(NV/32)
#define EDGE_BLOCKS 782      // ceil(NE*4/128)
__global__ __launch_bounds__(128) void gemms_kernel(const float* __restrict__ x,
                                                    const float* __restrict__ eattr) {
    if (blockIdx.x < NODE_BLOCKS) {
        __shared__ float shX[32][68];
        __shared__ float shWT[64][68];
        __shared__ float shUT[4][132];
        int t = threadIdx.x;
        int tx = t & 15, ty = t >> 4;
        int row0 = blockIdx.x * 32;
        for (int i = t; i < 512; i += 128) {
            int d = i >> 7, f = i & 127;
            shUT[d][f] = g_u1[f * 4 + d];
        }
        float acc[4][4] = {};
        float accA = 0.0f;
        int rA = t >> 2, dA = t & 3;
        for (int ch = 0; ch < 2; ch++) {
            int f0 = ch * 64;
            __syncthreads();
            for (int i = t; i < 2048; i += 128) {
                int r = i >> 6, f = i & 63;
                int v = row0 + r;
                shX[r][f] = (v < NV) ? x[v * FIN + f0 + f] : 0.0f;
            }
            for (int i = t; i < 4096; i += 128) {
                int f = i >> 6, c = i & 63;
                shWT[c][f] = g_WA[(f0 + f) * 64 + c];
            }
            __syncthreads();
            #pragma unroll
            for (int f4 = 0; f4 < 16; f4++) {
                float4 xr[4], wv[4];
                #pragma unroll
                for (int a = 0; a < 4; a++) xr[a] = *(const float4*)&shX[ty + 8 * a][f4 * 4];
                #pragma unroll
                for (int q = 0; q < 4; q++) wv[q] = *(const float4*)&shWT[tx + 16 * q][f4 * 4];
                #pragma unroll
                for (int a = 0; a < 4; a++)
                    #pragma unroll
                    for (int q = 0; q < 4; q++)
                        acc[a][q] += xr[a].x * wv[q].x + xr[a].y * wv[q].y
                                   + xr[a].z * wv[q].z + xr[a].w * wv[q].w;
            }
            #pragma unroll
            for (int f4 = 0; f4 < 16; f4++) {
                float4 xv = *(const float4*)&shX[rA][f4 * 4];
                float4 uv = *(const float4*)&shUT[dA][f0 + f4 * 4];
                accA += xv.x * uv.x + xv.y * uv.y + xv.z * uv.z + xv.w * uv.w;
            }
        }
        #pragma unroll
        for (int a = 0; a < 4; a++) {
            int v = row0 + ty + 8 * a;
            if (v >= NV) continue;
            #pragma unroll
            for (int q = 0; q < 4; q++) {
                int c = tx + 16 * q;
                g_P0[v * 64 + c] = acc[a][q] + g_bbG[c];
            }
        }
        int vA = row0 + rA;
        if (vA < NV) ((float*)g_a1)[vA * 4 + dA] = accA + g_ba1[dA];
    } else {
        int id = (blockIdx.x - NODE_BLOCKS) * 128 + threadIdx.x;
        if (id >= NE * 4) return;
        int e = id >> 2, d = id & 3;
        const float* row = eattr + e * FIN;
        float acc = g_ba2[d];
        #pragma unroll 8
        for (int f = 0; f < FIN; f++) acc += row[f] * g_u2[f * 4 + d];
        ((float*)g_a2)[id] = acc;
    }
}

// ---------------- sheaf scalars, scattered directly into CSR order ----------------
__global__ void s_kernel(const int* __restrict__ node_idx,
                         const int* __restrict__ edge_idx,
                         const float* __restrict__ bs) {
    int i = blockIdx.x * blockDim.x + threadIdx.x;
    if (i >= NNZ) return;
    float4 A = g_a1[node_idx[i]];
    float4 B = g_a2[edge_idx[i]];
    float4 r;
    r.x = tanhf(A.x + B.x + bs[0]);
    r.y = tanhf(A.y + B.y + bs[1]);
    r.z = tanhf(A.z + B.z + bs[2]);
    r.w = tanhf(A.w + B.w + bs[3]);
    g_se[g_slot_e[i]] = r;
    g_sv[g_slot_v[i]] = r;
}

// ---------------- aggregation: warp/segment, payload CSR, float2 channels --------
// lane l owns channels {2l, 2l+1}; both lie in stalk d = l>>3.
__device__ __forceinline__ float pick_s(const float4& s4, int dsel) {
    float lo = dsel < 1 ? s4.x : s4.y;
    float hi = dsel < 3 ? s4.z : s4.w;
    return dsel < 2 ? lo : hi;
}

__global__ void edge_agg(int src) {
    int w = (blockIdx.x * blockDim.x + threadIdx.x) >> 5;
    int lane = threadIdx.x & 31;
    if (w >= NE) return;
    const float* __restrict__ X = src ? g_H1 : g_P0;
    int beg = g_off_e[w], cnt = g_cnt_e[w];
    int dsel = lane >> 3;
    float2 acc = make_float2(0.0f, 0.0f);
    #pragma unroll 2
    for (int k = 0; k < cnt; k++) {
        int pos = beg + k;
        int v = g_vid_e[pos];
        float4 s4 = g_se[pos];
        float sd = pick_s(s4, dsel);
        float2 xr = *(const float2*)&X[v * 64 + lane * 2];
        acc.x += sd * xr.x;
        acc.y += sd * xr.y;
    }
    float inv = g_inv_e[w];
    ((float2*)g_m)[w * 32 + lane] = make_float2(acc.x * inv, acc.y * inv);
}

__global__ void node_agg(int layer, const float* __restrict__ b0) {
    int w = (blockIdx.x * blockDim.x + threadIdx.x) >> 5;
    int lane = threadIdx.x & 31;
    if (w >= NV) return;
    const float* __restrict__ Base = layer ? g_H1 : g_P0;
    float* __restrict__ Out = layer ? g_T : g_H1;
    int beg = g_off_v[w], cnt = g_cnt_v[w];
    int dsel = lane >> 3;
    float2 acc = make_float2(0.0f, 0.0f);
    #pragma unroll 2
    for (int k = 0; k < cnt; k++) {
        int pos = beg + k;
        int e = g_eid_v[pos];
        float4 s4 = g_sv[pos];
        float sd = pick_s(s4, dsel);
        float2 mr = ((const float2*)g_m)[e * 32 + lane];
        acc.x += sd * mr.x;
        acc.y += sd * mr.y;
    }
    float inv = g_inv_v[w];
    float2 base = ((const float2*)Base)[w * 32 + lane];
    float o0 = base.x - acc.x * inv;
    float o1 = base.y - acc.y * inv;
    if (layer == 0) {
        int c0 = lane * 2;
        o0 = fmaxf(o0 + b0[c0 & 15], 0.0f);
        o1 = fmaxf(o1 + b0[(c0 + 1) & 15], 0.0f);
    }
    ((float2*)Out)[w * 32 + lane] = make_float2(o0, o1);
}

// ---------------- final fused: out = relu(T @ blockdiag(W1) + b1) @ W2 ----------------
#define FK2_FLOATS (640 + 40 + 40 * 172 + 64 * 68 + 64 * 164)
__global__ __launch_bounds__(320, 2)
void final_kernel(const float* __restrict__ W1, const float* __restrict__ b1,
                  const float* __restrict__ W2, float* __restrict__ out) {
    extern __shared__ float sh[];
    float* shW1  = sh;                 // 640
    float* shb1  = sh + 640;           // 40
    float* shW2T = sh + 680;           // [j][k] stride 172
    float* shT   = sh + 7560;          // [r][c] stride 68 (reused as partials)
    float* shZ   = sh + 11912;         // [r][k] stride 164
    int t = threadIdx.x;
    for (int i = t; i < 640; i += 320) shW1[i] = W1[i];
    for (int i = t; i < 40; i += 320) shb1[i] = b1[i];
    for (int i = t; i < 6400; i += 320) {
        int k = i / 40, j = i % 40;
        shW2T[j * 172 + k] = W2[i];
    }
    int row0 = blockIdx.x * 64;
    for (int i = t; i < 4096; i += 320) {
        int r = i >> 6, c = i & 63;
        int v = row0 + r;
        shT[r * 68 + c] = (v < NV) ? g_T[v * 64 + c] : 0.0f;
    }
    __syncthreads();
    // Phase B: Z = relu(T @ blockdiag(W1) + b1)
    {
        int tx = t % 40, ty = t / 40;
        int d = tx / 10, cl = tx % 10;
        float zacc[8][4] = {};
        #pragma unroll
        for (int k = 0; k < 16; k++) {
            float tv[8], wv[4];
            #pragma unroll
            for (int a = 0; a < 8; a++) tv[a] = shT[(ty + 8 * a) * 68 + d * 16 + k];
            #pragma unroll
            for (int q = 0; q < 4; q++) wv[q] = shW1[k * 40 + cl + 10 * q];
            #pragma unroll
            for (int a = 0; a < 8; a++)
                #pragma unroll
                for (int q = 0; q < 4; q++) zacc[a][q] += tv[a] * wv[q];
        }
        #pragma unroll
        for (int a = 0; a < 8; a++)
            #pragma unroll
            for (int q = 0; q < 4; q++) {
                int j = cl + 10 * q;
                shZ[(ty + 8 * a) * 164 + d * 40 + j] = fmaxf(zacc[a][q] + shb1[j], 0.0f);
            }
    }
    __syncthreads();
    // Phase C: out = Z @ W2 (split-K halves). Mapping: col4 = g/16 (W2T rows
    // warp-broadcast), row4 = g%16, Z rows interleaved row4+16a (2-way max).
    {
        int g = t % 160, kh = t / 160;
        int col4 = g / 16, row4 = g % 16;
        int j0 = col4 * 4;
        float oa[4][4] = {};
        int kbeg = kh * 80;
        #pragma unroll 5
        for (int k4 = 0; k4 < 20; k4++) {
            int k = kbeg + k4 * 4;
            float4 zv[4], wv[4];
            #pragma unroll
            for (int a = 0; a < 4; a++) zv[a] = *(const float4*)&shZ[(row4 + 16 * a) * 164 + k];
            #pragma unroll
            for (int q = 0; q < 4; q++) wv[q] = *(const float4*)&shW2T[(j0 + q) * 172 + k];
            #pragma unroll
            for (int a = 0; a < 4; a++)
                #pragma unroll
                for (int q = 0; q < 4; q++)
                    oa[a][q] += zv[a].x * wv[q].x + zv[a].y * wv[q].y
                              + zv[a].z * wv[q].z + zv[a].w * wv[q].w;
        }
        float* shP = shT;                   // shT dead after phase B
        if (kh == 0) {
            #pragma unroll
            for (int a = 0; a < 4; a++)
                #pragma unroll
                for (int q = 0; q < 4; q++) shP[g * 16 + a * 4 + q] = oa[a][q];
        }
        __syncthreads();
        if (kh == 1) {
            #pragma unroll
            for (int a = 0; a < 4; a++) {
                int v = row0 + row4 + 16 * a;
                if (v < NV) {
                    #pragma unroll
                    for (int q = 0; q < 4; q++)
                        out[v * NC + j0 + q] = oa[a][q] + shP[g * 16 + a * 4 + q];
                }
            }
        }
    }
}

// ---------------- launch ----------------
extern "C" void kernel_launch(void* const* d_in, const int* in_sizes, int n_in,
                              void* d_out, int out_size) {
    const float* x        = (const float*)d_in[0];
    const float* eattr    = (const float*)d_in[1];
    const int*   node_idx = (const int*)d_in[2];
    const int*   edge_idx = (const int*)d_in[3];
    const float* Wlin     = (const float*)d_in[4];
    const float* blin     = (const float*)d_in[5];
    const float* w1       = (const float*)d_in[6];
    const float* w2       = (const float*)d_in[7];
    const float* bs       = (const float*)d_in[8];
    const float* W0       = (const float*)d_in[9];
    const float* b0       = (const float*)d_in[10];
    const float* W1       = (const float*)d_in[11];
    const float* b1       = (const float*)d_in[12];
    const float* W2       = (const float*)d_in[13];
    float* out = (float*)d_out;

    cudaFuncSetAttribute(final_kernel, cudaFuncAttributeMaxDynamicSharedMemorySize,
                         FK2_FLOATS * 4);

    int gZ = (NNZ + 255) / 256;

    init_kernel<<<ZBLK + FIN + 1, 128>>>(Wlin, blin, w1, w2, W0);
    count_deg<<<gZ, 256>>>(node_idx, edge_idx);
    scan_all<<<NBE + NBV, 1024>>>();
    fix_all<<<NBE + NBV, 1024>>>();
    fill_csr<<<gZ, 256>>>(node_idx, edge_idx);
    gemms_kernel<<<NODE_BLOCKS + EDGE_BLOCKS, 128>>>(x, eattr);
    s_kernel<<<gZ, 256>>>(node_idx, edge_idx, bs);

    edge_agg<<<(NE * 32 + 255) / 256, 256>>>(0);
    node_agg<<<(NV * 32 + 255) / 256, 256>>>(0, b0);
    edge_agg<<<(NE * 32 + 255) / 256, 256>>>(1);
    node_agg<<<(NV * 32 + 255) / 256, 256>>>(1, b0);

    final_kernel<<<(NV + 63) / 64, 320, FK2_FLOATS * 4>>>(W1, b1, W2, out);
}